// round 2
// baseline (speedup 1.0000x reference)
#include <cuda_runtime.h>

#define NGRAPHS 2048
#define NUMK    128
#define NE      1024
#define HD      32
#define ROWLEN  (NUMK + NE + 2)

// Edge template is identical across all graphs: build dst-sorted CSR once
// per launch into device globals (no allocation).
__device__ int g_csr[NE];          // packed: src | dst<<8 | eid<<16
__device__ int g_ptr[NUMK + 1];    // CSR row pointers by dst

// edge_index arrives as int32 (JAX x64 disabled) but guard for int64 layout:
// scan first 2048 int32 words (safe in both layouts); all-odd-words-zero
// implies little-endian int64.
__global__ void gcn_prep(const int* __restrict__ ew) {
    __shared__ unsigned char src_sh[NE], dst_sh[NE];
    __shared__ int cnt[NUMK];
    __shared__ int base_sh[NUMK + 1];
    __shared__ int odd_nonzero;
    int t = threadIdx.x;  // 128 threads
    if (t == 0) odd_nonzero = 0;
    __syncthreads();
    for (int i = t * 2 + 1; i < 2 * NE; i += 256)   // odd words in [0, 2048)
        if (ew[i] != 0) odd_nonzero = 1;
    __syncthreads();
    const bool is64 = (odd_nonzero == 0);
    for (int e = t; e < NE; e += 128) {
        int s, d;
        if (is64) { s = ew[2 * e]; d = ew[2 * (NE + e)]; }
        else      { s = ew[e];     d = ew[NE + e]; }
        src_sh[e] = (unsigned char)(s & 127);
        dst_sh[e] = (unsigned char)(d & 127);
    }
    cnt[t] = 0;
    __syncthreads();
    for (int e = t; e < NE; e += 128) atomicAdd(&cnt[dst_sh[e]], 1);
    __syncthreads();
    if (t == 0) {
        int acc = 0;
        for (int n = 0; n < NUMK; n++) { base_sh[n] = acc; acc += cnt[n]; }
        base_sh[NUMK] = acc;
    }
    __syncthreads();
    g_ptr[t] = base_sh[t];
    if (t == 0) g_ptr[NUMK] = base_sh[NUMK];
    cnt[t] = 0;
    __syncthreads();
    for (int e = t; e < NE; e += 128) {
        int d = dst_sh[e];
        int pos = base_sh[d] + atomicAdd(&cnt[d], 1);
        if (pos < NE)
            g_csr[pos] = (int)src_sh[e] | (d << 8) | (e << 16);
    }
}

// One CTA per graph. 256 threads = 8 warps; each warp owns 16 nodes.
// All three GCN layers fused; cross-node data lives in shared memory.
__global__ __launch_bounds__(256) void gcn_main(
    const float* __restrict__ Hx,
    const float* __restrict__ W1, const float* __restrict__ b1,
    const float* __restrict__ W2, const float* __restrict__ b2,
    const float* __restrict__ W3, const float* __restrict__ b3,
    float* __restrict__ out)
{
    __shared__ float  p_s[NUMK];
    __shared__ float  w_s[NE];
    __shared__ int    csr_s[NE];
    __shared__ int    ptr_s[NUMK + 1];
    __shared__ float  dinv_s[NUMK];
    __shared__ float  selfn_s[NUMK];
    __shared__ float2 ns_s[NE];          // (norm, src-as-float-bits) in CSR order
    __shared__ float  h_s[NUMK * HD];
    __shared__ float  h3_s[NUMK];
    __shared__ float  W1_s[HD], b1_s[HD], b2_s[HD], W3_s[HD];

    const int g    = blockIdx.x;
    const int tid  = threadIdx.x;
    const int lane = tid & 31;
    const int warp = tid >> 5;
    const float* row = Hx + (long long)g * ROWLEN;

    // ---- stage in inputs ----
    for (int i = tid; i < NUMK; i += 256) p_s[i] = row[i];
    for (int i = tid; i < NE; i += 256)  w_s[i] = row[NUMK + i];
    for (int i = tid; i < NE; i += 256)  csr_s[i] = g_csr[i];
    if (tid <= NUMK) ptr_s[tid] = g_ptr[tid];
    if (tid < HD) {
        W1_s[tid] = W1[tid]; b1_s[tid] = b1[tid];
        b2_s[tid] = b2[tid]; W3_s[tid] = W3[tid];
    }
    float W2col[HD];                     // W2[:, lane] held in registers
    #pragma unroll
    for (int k = 0; k < HD; k++) W2col[k] = __ldg(&W2[k * HD + lane]);
    __syncthreads();

    // ---- degree + symmetric norm (thread-per-node) ----
    if (tid < NUMK) {
        float deg = 1.0f;                // self-loop weight 1
        const int beg = ptr_s[tid], end = ptr_s[tid + 1];
        for (int s = beg; s < end; s++)
            deg += w_s[(csr_s[s] >> 16) & 1023];
        float di = (deg > 0.f) ? rsqrtf(deg) : 0.f;
        dinv_s[tid]  = di;
        selfn_s[tid] = di * di;
    }
    __syncthreads();
    for (int s = tid; s < NE; s += 256) {
        int pk = csr_s[s];
        int sn = pk & 255, dn = (pk >> 8) & 255, e = (pk >> 16) & 1023;
        ns_s[s] = make_float2(dinv_s[sn] * w_s[e] * dinv_s[dn],
                              __int_as_float(sn));
    }
    __syncthreads();

    // ---- layer 1: scalar aggregation, then expand through W1 ----
    float rx[16];                        // x1[node][lane] for this warp's nodes
    #pragma unroll
    for (int i = 0; i < 16; i++) {
        const int n = warp * 16 + i;
        const int beg = ptr_s[n], end = ptr_s[n + 1];
        float acc = 0.f;
        for (int s = beg + lane; s < end; s += 32) {
            float2 f = ns_s[s];
            acc += f.x * p_s[__float_as_int(f.y)];
        }
        #pragma unroll
        for (int o = 16; o; o >>= 1) acc += __shfl_xor_sync(0xffffffffu, acc, o);
        acc += selfn_s[n] * p_s[n];
        rx[i] = fmaxf(fmaf(acc, W1_s[lane], b1_s[lane]), 0.f);
    }

    // ---- layer 2 linear: h = x1 @ W2 via shuffle broadcast ----
    #pragma unroll
    for (int i = 0; i < 16; i++) {
        float acc = 0.f;
        #pragma unroll
        for (int k = 0; k < HD; k++)
            acc = fmaf(__shfl_sync(0xffffffffu, rx[i], k), W2col[k], acc);
        h_s[(warp * 16 + i) * HD + lane] = acc;
    }
    __syncthreads();

    // ---- layer 2 aggregation + relu, fused with layer 3 linear (dot W3) ----
    for (int i = 0; i < 16; i++) {
        const int n = warp * 16 + i;
        float acc = selfn_s[n] * h_s[n * HD + lane];
        const int beg = ptr_s[n], end = ptr_s[n + 1];
        for (int s = beg; s < end; s++) {
            float2 f = ns_s[s];
            acc = fmaf(f.x, h_s[__float_as_int(f.y) * HD + lane], acc);
        }
        float v = fmaxf(acc + b2_s[lane], 0.f) * W3_s[lane];
        #pragma unroll
        for (int o = 16; o; o >>= 1) v += __shfl_xor_sync(0xffffffffu, v, o);
        if (lane == 0) h3_s[n] = v;
    }
    __syncthreads();

    // ---- layer 3 aggregation -> output ----
    const float b3v = __ldg(&b3[0]);
    if (tid < NUMK) {
        const int n = tid;
        float acc = selfn_s[n] * h3_s[n];
        const int beg = ptr_s[n], end = ptr_s[n + 1];
        for (int s = beg; s < end; s++) {
            float2 f = ns_s[s];
            acc = fmaf(f.x, h3_s[__float_as_int(f.y)], acc);
        }
        out[(long long)g * NUMK + n] = acc + b3v;
    }
}

extern "C" void kernel_launch(void* const* d_in, const int* in_sizes, int n_in,
                              void* d_out, int out_size) {
    const float* Hx = (const float*)d_in[0];
    const int*   ei = (const int*)d_in[1];
    const float* W1 = (const float*)d_in[2];
    const float* b1 = (const float*)d_in[3];
    const float* W2 = (const float*)d_in[4];
    const float* b2 = (const float*)d_in[5];
    const float* W3 = (const float*)d_in[6];
    const float* b3 = (const float*)d_in[7];
    float* out = (float*)d_out;

    gcn_prep<<<1, 128>>>(ei);
    gcn_main<<<NGRAPHS, 256>>>(Hx, W1, b1, W2, b2, W3, b3, out);
}

// round 3
// speedup vs baseline: 1.5894x; 1.5894x over previous
#include <cuda_runtime.h>

#define NGRAPHS 2048
#define NUMK    128
#define NE      1024
#define HD      32
#define ROWLEN  (NUMK + NE + 2)

// Edge template identical across graphs: dst-sorted CSR built once per launch.
__device__ int g_csr[NE];          // packed: src | dst<<8 | eid<<16
__device__ int g_ptr[NUMK + 1];

// edge_index arrives as int32 (JAX x64 disabled) but guard for int64 layout.
__global__ void gcn_prep(const int* __restrict__ ew) {
    __shared__ unsigned char src_sh[NE], dst_sh[NE];
    __shared__ int cnt[NUMK];
    __shared__ int base_sh[NUMK + 1];
    __shared__ int odd_nonzero;
    int t = threadIdx.x;  // 128 threads
    if (t == 0) odd_nonzero = 0;
    __syncthreads();
    for (int i = t * 2 + 1; i < 2 * NE; i += 256)
        if (ew[i] != 0) odd_nonzero = 1;
    __syncthreads();
    const bool is64 = (odd_nonzero == 0);
    for (int e = t; e < NE; e += 128) {
        int s, d;
        if (is64) { s = ew[2 * e]; d = ew[2 * (NE + e)]; }
        else      { s = ew[e];     d = ew[NE + e]; }
        src_sh[e] = (unsigned char)(s & 127);
        dst_sh[e] = (unsigned char)(d & 127);
    }
    cnt[t] = 0;
    __syncthreads();
    for (int e = t; e < NE; e += 128) atomicAdd(&cnt[dst_sh[e]], 1);
    __syncthreads();
    if (t == 0) {
        int acc = 0;
        for (int n = 0; n < NUMK; n++) { base_sh[n] = acc; acc += cnt[n]; }
        base_sh[NUMK] = acc;
    }
    __syncthreads();
    g_ptr[t] = base_sh[t];
    if (t == 0) g_ptr[NUMK] = base_sh[NUMK];
    cnt[t] = 0;
    __syncthreads();
    for (int e = t; e < NE; e += 128) {
        int d = dst_sh[e];
        int pos = base_sh[d] + atomicAdd(&cnt[d], 1);
        if (pos < NE)
            g_csr[pos] = (int)src_sh[e] | (d << 8) | (e << 16);
    }
}

// One CTA per graph, 256 threads = 8 warps. All 3 GCN layers fused.
__global__ __launch_bounds__(256) void gcn_main(
    const float* __restrict__ Hx,
    const float* __restrict__ W1, const float* __restrict__ b1,
    const float* __restrict__ W2, const float* __restrict__ b2,
    const float* __restrict__ W3, const float* __restrict__ b3,
    float* __restrict__ out)
{
    __shared__ float  p_s[NUMK];
    __shared__ float  w_s[NE];
    __shared__ int    csr_s[NE];
    __shared__ int    ptr_s[NUMK + 1];
    __shared__ float  dinv_s[NUMK], selfn_s[NUMK], s1_s[NUMK], h3_s[NUMK];
    __shared__ float2 ns_s[NE];          // pass A: (w, src*8) ; pass B+: (norm, src*8)
    __shared__ __align__(16) float x1_s[NUMK * HD];
    __shared__ __align__(16) float h_s[NUMK * HD];
    __shared__ __align__(16) float W1_s[HD], b1_s[HD], b2_s[HD], W3_s[HD];

    const int g    = blockIdx.x;
    const int tid  = threadIdx.x;
    const int lane = tid & 31;
    const int warp = tid >> 5;
    const float* row = Hx + (long long)g * ROWLEN;   // 8B-aligned for all g

    // ---- stage inputs (vectorized) ----
    {
        const float2* rp = (const float2*)row;
        if (tid < 64) {
            float2 v = rp[tid];
            p_s[2 * tid] = v.x; p_s[2 * tid + 1] = v.y;
        }
        for (int i = tid; i < NE / 2; i += 256) {
            float2 v = rp[64 + i];
            w_s[2 * i] = v.x; w_s[2 * i + 1] = v.y;
        }
        const int4* rc = (const int4*)g_csr;
        for (int i = tid; i < NE / 4; i += 256)
            ((int4*)csr_s)[i] = rc[i];
        if (tid <= NUMK) ptr_s[tid] = g_ptr[tid];
        if (tid < HD) {
            W1_s[tid] = W1[tid]; b1_s[tid] = b1[tid];
            b2_s[tid] = b2[tid]; W3_s[tid] = W3[tid];
        }
    }
    __syncthreads();

    // ---- pass A: degree + stash (w, src*8) into ns in CSR order ----
    int begN = 0, endN = 0;
    if (tid < NUMK) {
        begN = ptr_s[tid]; endN = ptr_s[tid + 1];
        float deg = 1.0f;                // self-loop weight 1
        for (int s = begN; s < endN; s++) {
            int pk = csr_s[s];
            float wv = w_s[(pk >> 16) & 1023];
            ns_s[s] = make_float2(wv, __int_as_float((pk & 255) * 8));
            deg += wv;
        }
        float di = (deg > 0.f) ? rsqrtf(deg) : 0.f;
        dinv_s[tid]  = di;
        selfn_s[tid] = di * di;
    }
    __syncthreads();

    // ---- pass B: finalize norms + layer-1 scalar aggregation ----
    if (tid < NUMK) {
        const float di = dinv_s[tid];
        float acc = 0.f;
        for (int s = begN; s < endN; s++) {
            float2 f = ns_s[s];
            int sn = __float_as_int(f.y) >> 3;
            float norm = dinv_s[sn] * f.x * di;
            ns_s[s].x = norm;
            acc = fmaf(norm, p_s[sn], acc);
        }
        s1_s[tid] = fmaf(selfn_s[tid], p_s[tid], acc);
    }
    __syncthreads();

    // ---- pass C: x1 = relu(s1*W1 + b1); h = x1 @ W2 (float4 broadcast) ----
    {
        float W2col[HD];                 // W2[:, lane]
        #pragma unroll
        for (int k = 0; k < HD; k++) W2col[k] = __ldg(&W2[k * HD + lane]);
        const float w1l = W1_s[lane], b1l = b1_s[lane];
        const int nb = warp * 16;
        #pragma unroll
        for (int i = 0; i < 16; i++)
            x1_s[(nb + i) * HD + lane] =
                fmaxf(fmaf(s1_s[nb + i], w1l, b1l), 0.f);
        __syncwarp();
        #pragma unroll
        for (int i = 0; i < 16; i++) {
            const float4* xr = (const float4*)&x1_s[(nb + i) * HD];
            float acc = 0.f;
            #pragma unroll
            for (int q = 0; q < 8; q++) {
                float4 x4 = xr[q];
                acc = fmaf(x4.x, W2col[4 * q + 0], acc);
                acc = fmaf(x4.y, W2col[4 * q + 1], acc);
                acc = fmaf(x4.z, W2col[4 * q + 2], acc);
                acc = fmaf(x4.w, W2col[4 * q + 3], acc);
            }
            h_s[(nb + i) * HD + lane] = acc;
        }
    }
    __syncthreads();

    // ---- pass D: layer-2 aggregation (float4, 4 nodes/warp) + relu + dot W3 ----
    {
        const int li  = lane & 7;
        const int sub = lane >> 3;
        const float4 b24 = *(const float4*)&b2_s[li * 4];
        const float4 w34 = *(const float4*)&W3_s[li * 4];
        const float4* hb = (const float4*)h_s;
        #pragma unroll
        for (int ps = 0; ps < 4; ps++) {
            const int n = warp * 16 + ps * 4 + sub;
            float4 a = hb[n * 8 + li];
            const float sn = selfn_s[n];
            float4 acc = make_float4(sn * a.x, sn * a.y, sn * a.z, sn * a.w);
            const int beg = ptr_s[n], end = ptr_s[n + 1];
            for (int s = beg; s < end; s++) {
                float2 f = ns_s[s];
                float4 hv = hb[__float_as_int(f.y) + li];
                acc.x = fmaf(f.x, hv.x, acc.x);
                acc.y = fmaf(f.x, hv.y, acc.y);
                acc.z = fmaf(f.x, hv.z, acc.z);
                acc.w = fmaf(f.x, hv.w, acc.w);
            }
            float v = fmaxf(acc.x + b24.x, 0.f) * w34.x
                    + fmaxf(acc.y + b24.y, 0.f) * w34.y
                    + fmaxf(acc.z + b24.z, 0.f) * w34.z
                    + fmaxf(acc.w + b24.w, 0.f) * w34.w;
            v += __shfl_xor_sync(0xffffffffu, v, 4);
            v += __shfl_xor_sync(0xffffffffu, v, 2);
            v += __shfl_xor_sync(0xffffffffu, v, 1);
            if (li == 0) h3_s[n] = v;
        }
    }
    __syncthreads();

    // ---- pass E: layer-3 aggregation -> output ----
    if (tid < NUMK) {
        float acc = selfn_s[tid] * h3_s[tid];
        for (int s = begN; s < endN; s++) {
            float2 f = ns_s[s];
            acc = fmaf(f.x, h3_s[__float_as_int(f.y) >> 3], acc);
        }
        out[(long long)g * NUMK + tid] = acc + __ldg(&b3[0]);
    }
}

extern "C" void kernel_launch(void* const* d_in, const int* in_sizes, int n_in,
                              void* d_out, int out_size) {
    const float* Hx = (const float*)d_in[0];
    const int*   ei = (const int*)d_in[1];
    const float* W1 = (const float*)d_in[2];
    const float* b1 = (const float*)d_in[3];
    const float* W2 = (const float*)d_in[4];
    const float* b2 = (const float*)d_in[5];
    const float* W3 = (const float*)d_in[6];
    const float* b3 = (const float*)d_in[7];
    float* out = (float*)d_out;

    gcn_prep<<<1, 128>>>(ei);
    gcn_main<<<NGRAPHS, 256>>>(Hx, W1, b1, W2, b2, W3, b3, out);
}